// round 1
// baseline (speedup 1.0000x reference)
#include <cuda_runtime.h>

#define D      128
#define KS     9
#define L_IN   4096
#define L_OUT  4072
#define T_EFF  25
#define T12    17
#define BATCH  128

// Precomputed effective-conv tables (written by precompute kernels each launch)
__device__ float d_g1[4 * D * KS];     // [v][c1][k1]
__device__ float d_g2[4 * D * T12];    // [v][c2][t12]
__device__ float d_G [4 * D * T_EFF];  // [v][c][t]
__device__ float d_beff[D];

// ---------------------------------------------------------------------------
// g1[v,c1,k1] = sum_c0 W1[c1,c0,k1] * emb[v,c0]
__global__ void k_g1(const float* __restrict__ w1, const float* __restrict__ emb) {
    int k1 = blockIdx.x, c1 = threadIdx.x;
    __shared__ float es[4 * D];
    for (int i = threadIdx.x; i < 4 * D; i += D) es[i] = emb[i];
    __syncthreads();
    float a0 = 0.f, a1 = 0.f, a2 = 0.f, a3 = 0.f;
    for (int c0 = 0; c0 < D; c0++) {
        float w = w1[(c1 * D + c0) * KS + k1];
        a0 += w * es[0 * D + c0];
        a1 += w * es[1 * D + c0];
        a2 += w * es[2 * D + c0];
        a3 += w * es[3 * D + c0];
    }
    d_g1[(0 * D + c1) * KS + k1] = a0;
    d_g1[(1 * D + c1) * KS + k1] = a1;
    d_g1[(2 * D + c1) * KS + k1] = a2;
    d_g1[(3 * D + c1) * KS + k1] = a3;
}

// g2[v,c2,t] = sum_{k2+k1=t} sum_c1 W2[c2,c1,k2] * g1[v,c1,k1]
__global__ void k_g2(const float* __restrict__ w2) {
    int t = blockIdx.x, c2 = threadIdx.x;
    __shared__ float g1s[4 * D * KS];
    for (int i = threadIdx.x; i < 4 * D * KS; i += D) g1s[i] = d_g1[i];
    __syncthreads();
    float a0 = 0.f, a1 = 0.f, a2 = 0.f, a3 = 0.f;
    int klo = t - (KS - 1); if (klo < 0) klo = 0;
    int khi = t;            if (khi > KS - 1) khi = KS - 1;
    for (int k2 = klo; k2 <= khi; k2++) {
        int k1 = t - k2;
        for (int c1 = 0; c1 < D; c1++) {
            float w = w2[(c2 * D + c1) * KS + k2];
            a0 += w * g1s[(0 * D + c1) * KS + k1];
            a1 += w * g1s[(1 * D + c1) * KS + k1];
            a2 += w * g1s[(2 * D + c1) * KS + k1];
            a3 += w * g1s[(3 * D + c1) * KS + k1];
        }
    }
    d_g2[(0 * D + c2) * T12 + t] = a0;
    d_g2[(1 * D + c2) * T12 + t] = a1;
    d_g2[(2 * D + c2) * T12 + t] = a2;
    d_g2[(3 * D + c2) * T12 + t] = a3;
}

// G[v,c3,t] = sum_{k3+t12=t} sum_c2 W3[c3,c2,k3] * g2[v,c2,t12]
__global__ void k_g3(const float* __restrict__ w3) {
    int t = blockIdx.x, c3 = threadIdx.x;
    __shared__ float g2s[4 * D * T12];
    for (int i = threadIdx.x; i < 4 * D * T12; i += D) g2s[i] = d_g2[i];
    __syncthreads();
    float a0 = 0.f, a1 = 0.f, a2 = 0.f, a3 = 0.f;
    int klo = t - (T12 - 1); if (klo < 0) klo = 0;
    int khi = t;             if (khi > KS - 1) khi = KS - 1;
    for (int k3 = klo; k3 <= khi; k3++) {
        int t12 = t - k3;
        for (int c2 = 0; c2 < D; c2++) {
            float w = w3[(c3 * D + c2) * KS + k3];
            a0 += w * g2s[(0 * D + c2) * T12 + t12];
            a1 += w * g2s[(1 * D + c2) * T12 + t12];
            a2 += w * g2s[(2 * D + c2) * T12 + t12];
            a3 += w * g2s[(3 * D + c2) * T12 + t12];
        }
    }
    d_G[(0 * D + c3) * T_EFF + t] = a0;
    d_G[(1 * D + c3) * T_EFF + t] = a1;
    d_G[(2 * D + c3) * T_EFF + t] = a2;
    d_G[(3 * D + c3) * T_EFF + t] = a3;
}

// beff = b3 + sum(W3,k) @ (b2 + sum(W2,k) @ b1)
__global__ void k_bias(const float* __restrict__ w2, const float* __restrict__ w3,
                       const float* __restrict__ b1, const float* __restrict__ b2,
                       const float* __restrict__ b3) {
    __shared__ float bb2[D];
    int c = threadIdx.x;
    float s = b2[c];
    for (int c1 = 0; c1 < D; c1++) {
        float ws = 0.f;
        #pragma unroll
        for (int k = 0; k < KS; k++) ws += w2[(c * D + c1) * KS + k];
        s += ws * b1[c1];
    }
    bb2[c] = s;
    __syncthreads();
    float s3 = b3[c];
    for (int c2 = 0; c2 < D; c2++) {
        float ws = 0.f;
        #pragma unroll
        for (int k = 0; k < KS; k++) ws += w3[(c * D + c2) * KS + k];
        s3 += ws * bb2[c2];
    }
    d_beff[c] = s3;
}

// ---------------------------------------------------------------------------
// Main kernel: one CTA per batch row.
__global__ __launch_bounds__(1024) void k_main(
    const int*   __restrict__ tokens,
    const float* __restrict__ wq, const float* __restrict__ bq,
    const float* __restrict__ wk, const float* __restrict__ bk,
    const float* __restrict__ wv, const float* __restrict__ bv,
    float* __restrict__ out)
{
    __shared__ float sc[L_OUT];          // scores -> exp weights (also matvec scratch)
    __shared__ float Hs[128];            // H[v*25+t]
    __shared__ float As[128];            // A[v*25+t]
    __shared__ float cntf[128];          // cnt_t[v] as float, [t*4+v]
    __shared__ float rm[D], qv[D], qks[D], sv[D];
    __shared__ float redf[40];
    __shared__ int   cnti[4];
    __shared__ unsigned char tok[L_IN];

    const int b = blockIdx.x, tid = threadIdx.x;
    const int lane = tid & 31, warp = tid >> 5;

    // Phase 0: stage tokens as bytes
    const int* tb = tokens + b * L_IN;
    for (int i = tid; i < L_IN; i += 1024) tok[i] = (unsigned char)tb[i];
    if (tid < 4) cnti[tid] = 0;
    __syncthreads();

    // Phase 1a: full-sequence token counts
    {
        int l0 = 0, l1 = 0, l2 = 0, l3 = 0;
        for (int i = tid; i < L_IN; i += 1024) {
            int v = tok[i];
            l0 += (v == 0); l1 += (v == 1); l2 += (v == 2); l3 += (v == 3);
        }
        #pragma unroll
        for (int o = 16; o; o >>= 1) {
            l0 += __shfl_xor_sync(0xffffffffu, l0, o);
            l1 += __shfl_xor_sync(0xffffffffu, l1, o);
            l2 += __shfl_xor_sync(0xffffffffu, l2, o);
            l3 += __shfl_xor_sync(0xffffffffu, l3, o);
        }
        if (lane == 0) {
            atomicAdd(&cnti[0], l0); atomicAdd(&cnti[1], l1);
            atomicAdd(&cnti[2], l2); atomicAdd(&cnti[3], l3);
        }
    }
    __syncthreads();

    // Phase 1b: per-tap windowed counts cnt_t[v] = count of v in [t, t+L_OUT)
    if (warp == 0 && lane < T_EFF) {
        int t = lane;
        int c0 = cnti[0], c1 = cnti[1], c2 = cnti[2], c3 = cnti[3];
        for (int j = 0; j < t; j++) {
            int v = tok[j];
            c0 -= (v == 0); c1 -= (v == 1); c2 -= (v == 2); c3 -= (v == 3);
        }
        for (int j = t + L_OUT; j < L_IN; j++) {
            int v = tok[j];
            c0 -= (v == 0); c1 -= (v == 1); c2 -= (v == 2); c3 -= (v == 3);
        }
        cntf[t * 4 + 0] = (float)c0; cntf[t * 4 + 1] = (float)c1;
        cntf[t * 4 + 2] = (float)c2; cntf[t * 4 + 3] = (float)c3;
    }
    __syncthreads();

    // Phase 1c: read_mean
    if (tid < D) {
        float acc = 0.f;
        #pragma unroll
        for (int t = 0; t < T_EFF; t++) {
            acc += cntf[t * 4 + 0] * d_G[(0 * D + tid) * T_EFF + t]
                 + cntf[t * 4 + 1] * d_G[(1 * D + tid) * T_EFF + t]
                 + cntf[t * 4 + 2] * d_G[(2 * D + tid) * T_EFF + t]
                 + cntf[t * 4 + 3] * d_G[(3 * D + tid) * T_EFF + t];
        }
        rm[tid] = d_beff[tid] + acc * (1.0f / (float)L_OUT);
    }
    __syncthreads();

    // Phase 2: q = Wq @ rm + bq  (warp-per-output dot products, coalesced)
    for (int c = warp; c < D; c += 32) {
        float s = 0.f;
        #pragma unroll
        for (int j = 0; j < 4; j++) { int i = lane + 32 * j; s += wq[c * D + i] * rm[i]; }
        #pragma unroll
        for (int o = 16; o; o >>= 1) s += __shfl_xor_sync(0xffffffffu, s, o);
        if (lane == 0) qv[c] = s + bq[c];
    }
    __syncthreads();

    // Phase 3: qk = Wk^T @ q  (coalesced column sums, scratch in sc[])
    {
        int g = tid >> 7, i = tid & 127;
        float s = 0.f;
        #pragma unroll
        for (int o = 0; o < 16; o++) s += wk[(g * 16 + o) * D + i] * qv[g * 16 + o];
        sc[g * D + i] = s;
    }
    __syncthreads();
    if (tid < D) {
        float s = 0.f;
        #pragma unroll
        for (int g = 0; g < 8; g++) s += sc[g * D + tid];
        qks[tid] = s;
    }
    __syncthreads();

    // Phase H: H[v,t] = qk . G[v,:,t]   (100 warp-parallel dot products)
    for (int pr = warp; pr < 100; pr += 32) {
        int v = pr / T_EFF, t = pr % T_EFF;
        float s = 0.f;
        #pragma unroll
        for (int j = 0; j < 4; j++) {
            int c = lane + 32 * j;
            s += qks[c] * d_G[(v * D + c) * T_EFF + t];
        }
        #pragma unroll
        for (int o = 16; o; o >>= 1) s += __shfl_xor_sync(0xffffffffu, s, o);
        if (lane == 0) Hs[v * T_EFF + t] = s;
    }
    __syncthreads();

    // Phase 4: scores[l] = (sum_t H[tok[l+t],t]) / sqrt(D)
    const float isq = 0.088388347648318447f;  // 1/sqrt(128)
    float lmax = -1e30f;
    for (int l = tid; l < L_OUT; l += 1024) {
        float s = 0.f;
        #pragma unroll
        for (int t = 0; t < T_EFF; t++) s += Hs[(int)tok[l + t] * T_EFF + t];
        s *= isq;
        sc[l] = s;
        lmax = fmaxf(lmax, s);
    }
    #pragma unroll
    for (int o = 16; o; o >>= 1) lmax = fmaxf(lmax, __shfl_xor_sync(0xffffffffu, lmax, o));
    if (lane == 0) redf[warp] = lmax;
    __syncthreads();
    if (tid < 32) {
        float m = redf[tid];
        #pragma unroll
        for (int o = 16; o; o >>= 1) m = fmaxf(m, __shfl_xor_sync(0xffffffffu, m, o));
        if (tid == 0) redf[33] = m;
    }
    __syncthreads();
    const float smax = redf[33];

    // Phase 5: exp + sum (softmax denominator; normalization folded into sv)
    float lsum = 0.f;
    for (int l = tid; l < L_OUT; l += 1024) {
        float e = __expf(sc[l] - smax);
        sc[l] = e;
        lsum += e;
    }
    __syncthreads();
    #pragma unroll
    for (int o = 16; o; o >>= 1) lsum += __shfl_xor_sync(0xffffffffu, lsum, o);
    if (lane == 0) redf[warp] = lsum;
    __syncthreads();
    if (tid < 32) {
        float m = redf[tid];
        #pragma unroll
        for (int o = 16; o; o >>= 1) m += __shfl_xor_sync(0xffffffffu, m, o);
        if (tid == 0) redf[34] = m;
    }
    __syncthreads();
    const float invZ = 1.0f / redf[34];

    // Phase 6: A[v,t] = sum_{p: tok[p]=v} e[p-t]   (one warp per tap t, no atomics)
    if (tid < 128) As[tid] = 0.f;
    __syncthreads();
    if (warp < T_EFF) {
        int t = warp;
        float a0 = 0.f, a1 = 0.f, a2 = 0.f, a3 = 0.f;
        for (int p = lane; p < L_IN; p += 32) {
            int l = p - t;
            if ((unsigned)l < (unsigned)L_OUT) {
                float e = sc[l];
                int v = tok[p];
                a0 += (v == 0) ? e : 0.f;
                a1 += (v == 1) ? e : 0.f;
                a2 += (v == 2) ? e : 0.f;
                a3 += (v == 3) ? e : 0.f;
            }
        }
        #pragma unroll
        for (int o = 16; o; o >>= 1) {
            a0 += __shfl_xor_sync(0xffffffffu, a0, o);
            a1 += __shfl_xor_sync(0xffffffffu, a1, o);
            a2 += __shfl_xor_sync(0xffffffffu, a2, o);
            a3 += __shfl_xor_sync(0xffffffffu, a3, o);
        }
        if (lane == 0) {
            As[0 * T_EFF + t] = a0; As[1 * T_EFF + t] = a1;
            As[2 * T_EFF + t] = a2; As[3 * T_EFF + t] = a3;
        }
    }
    __syncthreads();

    // Phase 7: sv = beff + (1/Z) * sum_{v,t} A[v,t] * G[v,:,t]
    if (tid < D) {
        float acc = 0.f;
        #pragma unroll
        for (int t = 0; t < T_EFF; t++) {
            acc += As[0 * T_EFF + t] * d_G[(0 * D + tid) * T_EFF + t]
                 + As[1 * T_EFF + t] * d_G[(1 * D + tid) * T_EFF + t]
                 + As[2 * T_EFF + t] * d_G[(2 * D + tid) * T_EFF + t]
                 + As[3 * T_EFF + t] * d_G[(3 * D + tid) * T_EFF + t];
        }
        sv[tid] = d_beff[tid] + acc * invZ;
    }
    __syncthreads();

    // Phase 8: out = Wv @ sv + bv
    for (int c = warp; c < D; c += 32) {
        float s = 0.f;
        #pragma unroll
        for (int j = 0; j < 4; j++) { int i = lane + 32 * j; s += wv[c * D + i] * sv[i]; }
        #pragma unroll
        for (int o = 16; o; o >>= 1) s += __shfl_xor_sync(0xffffffffu, s, o);
        if (lane == 0) out[b * D + c] = s + bv[c];
    }
}

// ---------------------------------------------------------------------------
extern "C" void kernel_launch(void* const* d_in, const int* in_sizes, int n_in,
                              void* d_out, int out_size) {
    const int*   tokens = (const int*)  d_in[0];
    const float* emb    = (const float*)d_in[1];
    const float* w1     = (const float*)d_in[2];
    const float* b1     = (const float*)d_in[3];
    const float* wr     = (const float*)d_in[4];
    const float* br     = (const float*)d_in[5];
    const float* wq     = (const float*)d_in[6];
    const float* bq     = (const float*)d_in[7];
    const float* wk     = (const float*)d_in[8];
    const float* bk     = (const float*)d_in[9];
    const float* wv     = (const float*)d_in[10];
    const float* bv     = (const float*)d_in[11];

    const float* w2 = wr;
    const float* w3 = wr + D * D * KS;
    const float* b2 = br;
    const float* b3 = br + D;

    k_g1<<<KS, D>>>(w1, emb);
    k_g2<<<T12, D>>>(w2);
    k_g3<<<T_EFF, D>>>(w3);
    k_bias<<<1, D>>>(w2, w3, b1, b2, b3);
    k_main<<<BATCH, 1024>>>(tokens, wq, bq, wk, bk, wv, bv, (float*)d_out);
}

// round 2
// speedup vs baseline: 6.6608x; 6.6608x over previous
#include <cuda_runtime.h>

#define D      128
#define KS     9
#define L_IN   4096
#define L_OUT  4072
#define T_EFF  25
#define T12    17
#define BATCH  128
#define ROW    (D * KS)   // 1152 = flattened (c_in, k) row length

// Precomputed effective-conv tables
__device__ float d_g1[4 * D * KS];     // [v][c1][k1]
__device__ float d_g2[4 * D * T12];    // [v][c2][t12]
__device__ float d_G [4 * D * T_EFF];  // [v][c][t]
__device__ float d_bb2[D];
__device__ float d_beff[D];

// ---------------------------------------------------------------------------
// K1: blocks [0,128): g1 for c1=blockIdx.x (stage W1 row coalesced, smem dots)
//     blocks [128,144): bias stage 1: bb2 = b2 + rowsum(W2) @ b1
__global__ __launch_bounds__(256) void k_pre1(
    const float* __restrict__ w1, const float* __restrict__ emb,
    const float* __restrict__ w2, const float* __restrict__ b1,
    const float* __restrict__ b2)
{
    const int tid = threadIdx.x, lane = tid & 31, warp = tid >> 5;
    if (blockIdx.x < 128) {
        // ---- g1[v,c1,k1] = sum_c0 W1[c1,c0,k1] * emb[v,c0]
        const int c1 = blockIdx.x;
        __shared__ float ws[ROW];
        __shared__ float es[4 * D];
        const float* wrow = w1 + c1 * ROW;
        for (int i = tid; i < ROW; i += 256) ws[i] = wrow[i];
        for (int i = tid; i < 4 * D; i += 256) es[i] = emb[i];
        __syncthreads();
        if (tid < 36) {
            const int v = tid / KS, k1 = tid % KS;
            float s = 0.f;
            #pragma unroll 8
            for (int c0 = 0; c0 < D; c0++) s += ws[c0 * KS + k1] * es[v * D + c0];
            d_g1[(v * D + c1) * KS + k1] = s;
        }
    } else {
        // ---- bb2[c] = b2[c] + sum_{c1,k} W2[c,c1,k] * b1[c1]
        __shared__ float b1s[D];
        if (tid < D) b1s[tid] = b1[tid];
        __syncthreads();
        const int c = (blockIdx.x - 128) * 8 + warp;   // 16 blocks * 8 warps = 128
        const float* wrow = w2 + c * ROW;
        float s = 0.f;
        #pragma unroll
        for (int i = 0; i < ROW / 32; i++) {
            int idx = lane + 32 * i;
            s += wrow[idx] * b1s[idx / KS];
        }
        #pragma unroll
        for (int o = 16; o; o >>= 1) s += __shfl_xor_sync(0xffffffffu, s, o);
        if (lane == 0) d_bb2[c] = b2[c] + s;
    }
}

// ---------------------------------------------------------------------------
// K2: g2[v,c2,t] = sum over flattened row W2[c2,:,:] . X  with
//     X[c1*9+k2] = g1[v,c1,t-k2] (valid) else 0.   grid = 68 (v,t)
__global__ __launch_bounds__(256) void k_pre2(const float* __restrict__ w2)
{
    const int tid = threadIdx.x, lane = tid & 31, warp = tid >> 5;
    const int v = blockIdx.x & 3, t = blockIdx.x >> 2;   // t in [0,17)
    __shared__ float Xs[ROW];
    for (int i = tid; i < ROW; i += 256) {
        int c1 = i / KS, k2 = i % KS, k1 = t - k2;
        Xs[i] = ((unsigned)k1 < (unsigned)KS) ? d_g1[(v * D + c1) * KS + k1] : 0.f;
    }
    __syncthreads();
    for (int j = 0; j < 16; j++) {                        // 8 warps * 16 = 128 c2
        const int c2 = warp * 16 + j;
        const float* wrow = w2 + c2 * ROW;
        float s = 0.f;
        #pragma unroll
        for (int i = 0; i < ROW / 32; i++) {
            int idx = lane + 32 * i;
            s += wrow[idx] * Xs[idx];
        }
        #pragma unroll
        for (int o = 16; o; o >>= 1) s += __shfl_xor_sync(0xffffffffu, s, o);
        if (lane == 0) d_g2[(v * D + c2) * T12 + t] = s;
    }
}

// ---------------------------------------------------------------------------
// K3: blocks [0,100): G[v,c3,t] with X[c2*9+k3] = g2[v,c2,t-k3]
//     blocks [100,116): bias stage 2: beff = b3 + rowsum(W3) @ bb2
__global__ __launch_bounds__(256) void k_pre3(
    const float* __restrict__ w3, const float* __restrict__ b3)
{
    const int tid = threadIdx.x, lane = tid & 31, warp = tid >> 5;
    if (blockIdx.x < 100) {
        const int v = blockIdx.x & 3, t = blockIdx.x >> 2;   // t in [0,25)
        __shared__ float Xs[ROW];
        for (int i = tid; i < ROW; i += 256) {
            int c2 = i / KS, k3 = i % KS, t12 = t - k3;
            Xs[i] = ((unsigned)t12 < (unsigned)T12) ? d_g2[(v * D + c2) * T12 + t12] : 0.f;
        }
        __syncthreads();
        for (int j = 0; j < 16; j++) {
            const int c3 = warp * 16 + j;
            const float* wrow = w3 + c3 * ROW;
            float s = 0.f;
            #pragma unroll
            for (int i = 0; i < ROW / 32; i++) {
                int idx = lane + 32 * i;
                s += wrow[idx] * Xs[idx];
            }
            #pragma unroll
            for (int o = 16; o; o >>= 1) s += __shfl_xor_sync(0xffffffffu, s, o);
            if (lane == 0) d_G[(v * D + c3) * T_EFF + t] = s;
        }
    } else {
        __shared__ float bbs[D];
        if (tid < D) bbs[tid] = d_bb2[tid];
        __syncthreads();
        const int c = (blockIdx.x - 100) * 8 + warp;
        const float* wrow = w3 + c * ROW;
        float s = 0.f;
        #pragma unroll
        for (int i = 0; i < ROW / 32; i++) {
            int idx = lane + 32 * i;
            s += wrow[idx] * bbs[idx / KS];
        }
        #pragma unroll
        for (int o = 16; o; o >>= 1) s += __shfl_xor_sync(0xffffffffu, s, o);
        if (lane == 0) d_beff[c] = b3[c] + s;
    }
}

// ---------------------------------------------------------------------------
// Main kernel: one CTA per batch row.
__global__ __launch_bounds__(1024) void k_main(
    const int*   __restrict__ tokens,
    const float* __restrict__ wq, const float* __restrict__ bq,
    const float* __restrict__ wk, const float* __restrict__ bk,
    const float* __restrict__ wv, const float* __restrict__ bv,
    float* __restrict__ out)
{
    __shared__ float sc[L_OUT];          // scores -> exp weights (also matvec scratch)
    __shared__ float Hs[128];            // H laid out [t*4 + v]
    __shared__ float As[128];            // A[v*25+t]
    __shared__ float cntf[128];          // cnt_t[v] as float, [t*4+v]
    __shared__ float rm[D], qv[D], qks[D], sv[D];
    __shared__ float redf[40];
    __shared__ int   cnti[4];
    __shared__ unsigned tok_u[L_IN / 4]; // tokens packed as bytes
    unsigned char* tok = (unsigned char*)tok_u;

    const int b = blockIdx.x, tid = threadIdx.x;
    const int lane = tid & 31, warp = tid >> 5;

    // Phase 0: stage tokens as packed bytes (one int4 load, one STS per thread)
    {
        const int4* tb4 = (const int4*)(tokens + b * L_IN);
        int4 w = tb4[tid];
        tok_u[tid] = (unsigned)w.x | ((unsigned)w.y << 8) |
                     ((unsigned)w.z << 16) | ((unsigned)w.w << 24);
    }
    if (tid < 4) cnti[tid] = 0;
    __syncthreads();

    // Phase 1a: full-sequence token counts (4 tokens per thread from packed word)
    {
        unsigned u = tok_u[tid];
        int l0 = 0, l1 = 0, l2 = 0, l3 = 0;
        #pragma unroll
        for (int j = 0; j < 4; j++) {
            int v = (u >> (8 * j)) & 3;
            l0 += (v == 0); l1 += (v == 1); l2 += (v == 2); l3 += (v == 3);
        }
        #pragma unroll
        for (int o = 16; o; o >>= 1) {
            l0 += __shfl_xor_sync(0xffffffffu, l0, o);
            l1 += __shfl_xor_sync(0xffffffffu, l1, o);
            l2 += __shfl_xor_sync(0xffffffffu, l2, o);
            l3 += __shfl_xor_sync(0xffffffffu, l3, o);
        }
        if (lane == 0) {
            atomicAdd(&cnti[0], l0); atomicAdd(&cnti[1], l1);
            atomicAdd(&cnti[2], l2); atomicAdd(&cnti[3], l3);
        }
    }
    __syncthreads();

    // Phase 1b: per-tap windowed counts cnt_t[v] = count of v in [t, t+L_OUT)
    if (warp == 0 && lane < T_EFF) {
        int t = lane;
        int c0 = cnti[0], c1 = cnti[1], c2 = cnti[2], c3 = cnti[3];
        for (int j = 0; j < t; j++) {
            int v = tok[j];
            c0 -= (v == 0); c1 -= (v == 1); c2 -= (v == 2); c3 -= (v == 3);
        }
        for (int j = t + L_OUT; j < L_IN; j++) {
            int v = tok[j];
            c0 -= (v == 0); c1 -= (v == 1); c2 -= (v == 2); c3 -= (v == 3);
        }
        cntf[t * 4 + 0] = (float)c0; cntf[t * 4 + 1] = (float)c1;
        cntf[t * 4 + 2] = (float)c2; cntf[t * 4 + 3] = (float)c3;
    }
    __syncthreads();

    // Phase 1c: read_mean
    if (tid < D) {
        float acc = 0.f;
        #pragma unroll
        for (int t = 0; t < T_EFF; t++) {
            acc += cntf[t * 4 + 0] * d_G[(0 * D + tid) * T_EFF + t]
                 + cntf[t * 4 + 1] * d_G[(1 * D + tid) * T_EFF + t]
                 + cntf[t * 4 + 2] * d_G[(2 * D + tid) * T_EFF + t]
                 + cntf[t * 4 + 3] * d_G[(3 * D + tid) * T_EFF + t];
        }
        rm[tid] = d_beff[tid] + acc * (1.0f / (float)L_OUT);
    }
    __syncthreads();

    // Phase 2: q = Wq @ rm + bq
    for (int c = warp; c < D; c += 32) {
        float s = 0.f;
        #pragma unroll
        for (int j = 0; j < 4; j++) { int i = lane + 32 * j; s += wq[c * D + i] * rm[i]; }
        #pragma unroll
        for (int o = 16; o; o >>= 1) s += __shfl_xor_sync(0xffffffffu, s, o);
        if (lane == 0) qv[c] = s + bq[c];
    }
    __syncthreads();

    // Phase 3: qk = Wk^T @ q  (coalesced column sums, scratch in sc[])
    {
        int g = tid >> 7, i = tid & 127;
        float s = 0.f;
        #pragma unroll
        for (int o = 0; o < 16; o++) s += wk[(g * 16 + o) * D + i] * qv[g * 16 + o];
        sc[g * D + i] = s;
    }
    __syncthreads();
    if (tid < D) {
        float s = 0.f;
        #pragma unroll
        for (int g = 0; g < 8; g++) s += sc[g * D + tid];
        qks[tid] = s;
    }
    __syncthreads();

    // Phase H: H[t*4+v] = qk . G[v,:,t]  (100 warp dot products)
    for (int pr = warp; pr < 100; pr += 32) {
        int v = pr / T_EFF, t = pr % T_EFF;
        float s = 0.f;
        #pragma unroll
        for (int j = 0; j < 4; j++) {
            int c = lane + 32 * j;
            s += qks[c] * d_G[(v * D + c) * T_EFF + t];
        }
        #pragma unroll
        for (int o = 16; o; o >>= 1) s += __shfl_xor_sync(0xffffffffu, s, o);
        if (lane == 0) Hs[t * 4 + v] = s;
    }
    __syncthreads();

    // Phase 4: scores. Thread handles 4 consecutive l from a 28-byte reg window.
    const float isq = 0.088388347648318447f;  // 1/sqrt(128)
    float lmax = -1e30f;
    if (tid < 1018) {                          // 1018*4 = 4072 = L_OUT
        const int l0 = tid * 4;
        unsigned u[7];
        #pragma unroll
        for (int j = 0; j < 7; j++) u[j] = tok_u[(l0 >> 2) + j];
        #pragma unroll
        for (int k = 0; k < 4; k++) {
            float s = 0.f;
            #pragma unroll
            for (int t = 0; t < T_EFF; t++) {
                int j = k + t;
                int v = (u[j >> 2] >> ((j & 3) * 8)) & 3;
                s += Hs[t * 4 + v];
            }
            s *= isq;
            sc[l0 + k] = s;
            lmax = fmaxf(lmax, s);
        }
    }
    #pragma unroll
    for (int o = 16; o; o >>= 1) lmax = fmaxf(lmax, __shfl_xor_sync(0xffffffffu, lmax, o));
    if (lane == 0) redf[warp] = lmax;
    __syncthreads();
    if (tid < 32) {
        float m = redf[tid];
        #pragma unroll
        for (int o = 16; o; o >>= 1) m = fmaxf(m, __shfl_xor_sync(0xffffffffu, m, o));
        if (tid == 0) redf[33] = m;
    }
    __syncthreads();
    const float smax = redf[33];

    // Phase 5: exp + sum
    float lsum = 0.f;
    for (int l = tid; l < L_OUT; l += 1024) {
        float e = __expf(sc[l] - smax);
        sc[l] = e;
        lsum += e;
    }
    __syncthreads();
    #pragma unroll
    for (int o = 16; o; o >>= 1) lsum += __shfl_xor_sync(0xffffffffu, lsum, o);
    if (lane == 0) redf[warp] = lsum;
    __syncthreads();
    if (tid < 32) {
        float m = redf[tid];
        #pragma unroll
        for (int o = 16; o; o >>= 1) m += __shfl_xor_sync(0xffffffffu, m, o);
        if (tid == 0) redf[34] = m;
    }
    __syncthreads();
    const float invZ = 1.0f / redf[34];

    // Phase 6: A[v,t] = sum_{p: tok[p]=v} e[p-t]   (warp per tap, no atomics)
    if (tid < 128) As[tid] = 0.f;
    __syncthreads();
    if (warp < T_EFF) {
        int t = warp;
        float a0 = 0.f, a1 = 0.f, a2 = 0.f, a3 = 0.f;
        for (int p = lane; p < L_IN; p += 32) {
            int l = p - t;
            if ((unsigned)l < (unsigned)L_OUT) {
                float e = sc[l];
                int v = tok[p];
                a0 += (v == 0) ? e : 0.f;
                a1 += (v == 1) ? e : 0.f;
                a2 += (v == 2) ? e : 0.f;
                a3 += (v == 3) ? e : 0.f;
            }
        }
        #pragma unroll
        for (int o = 16; o; o >>= 1) {
            a0 += __shfl_xor_sync(0xffffffffu, a0, o);
            a1 += __shfl_xor_sync(0xffffffffu, a1, o);
            a2 += __shfl_xor_sync(0xffffffffu, a2, o);
            a3 += __shfl_xor_sync(0xffffffffu, a3, o);
        }
        if (lane == 0) {
            As[0 * T_EFF + t] = a0; As[1 * T_EFF + t] = a1;
            As[2 * T_EFF + t] = a2; As[3 * T_EFF + t] = a3;
        }
    }
    __syncthreads();

    // Phase 7: sv = beff + (1/Z) * sum_{v,t} A[v,t] * G[v,:,t]
    if (tid < D) {
        float acc = 0.f;
        #pragma unroll
        for (int t = 0; t < T_EFF; t++) {
            acc += As[0 * T_EFF + t] * d_G[(0 * D + tid) * T_EFF + t]
                 + As[1 * T_EFF + t] * d_G[(1 * D + tid) * T_EFF + t]
                 + As[2 * T_EFF + t] * d_G[(2 * D + tid) * T_EFF + t]
                 + As[3 * T_EFF + t] * d_G[(3 * D + tid) * T_EFF + t];
        }
        sv[tid] = d_beff[tid] + acc * invZ;
    }
    __syncthreads();

    // Phase 8: out = Wv @ sv + bv
    for (int c = warp; c < D; c += 32) {
        float s = 0.f;
        #pragma unroll
        for (int j = 0; j < 4; j++) { int i = lane + 32 * j; s += wv[c * D + i] * sv[i]; }
        #pragma unroll
        for (int o = 16; o; o >>= 1) s += __shfl_xor_sync(0xffffffffu, s, o);
        if (lane == 0) out[b * D + c] = s + bv[c];
    }
}

// ---------------------------------------------------------------------------
extern "C" void kernel_launch(void* const* d_in, const int* in_sizes, int n_in,
                              void* d_out, int out_size) {
    const int*   tokens = (const int*)  d_in[0];
    const float* emb    = (const float*)d_in[1];
    const float* w1     = (const float*)d_in[2];
    const float* b1     = (const float*)d_in[3];
    const float* wr     = (const float*)d_in[4];
    const float* br     = (const float*)d_in[5];
    const float* wq     = (const float*)d_in[6];
    const float* bq     = (const float*)d_in[7];
    const float* wk     = (const float*)d_in[8];
    const float* bk     = (const float*)d_in[9];
    const float* wv     = (const float*)d_in[10];
    const float* bv     = (const float*)d_in[11];

    const float* w2 = wr;
    const float* w3 = wr + D * D * KS;
    const float* b2 = br;
    const float* b3 = br + D;

    k_pre1<<<144, 256>>>(w1, emb, w2, b1, b2);
    k_pre2<<<68, 256>>>(w2);
    k_pre3<<<116, 256>>>(w3, b3);
    k_main<<<BATCH, 1024>>>(tokens, wq, bq, wk, bk, wv, bv, (float*)d_out);
}

// round 3
// speedup vs baseline: 8.3041x; 1.2467x over previous
#include <cuda_runtime.h>

#define D      128
#define KS     9
#define L_IN   4096
#define L_OUT  4072
#define T_EFF  25
#define T12    17
#define BATCH  128
#define ROW    (D * KS)   // 1152

// Precomputed tables
__device__ float d_g1[4 * D * KS];        // [v][c1][k1]
__device__ float d_g2[4 * D * T12];       // [v][c2][t12]
__device__ float d_G [T_EFF * 4 * D];     // TRANSPOSED: [(t*4+v)][c]
__device__ float d_bb2[D];
__device__ float d_beff[D];

// ---------------------------------------------------------------------------
// pre1: blocks [0,128): g1 for c1=blockIdx; blocks [128,144): bb2
__global__ __launch_bounds__(256) void k_pre1(
    const float* __restrict__ w1, const float* __restrict__ emb,
    const float* __restrict__ w2, const float* __restrict__ b1,
    const float* __restrict__ b2)
{
    const int tid = threadIdx.x, lane = tid & 31, warp = tid >> 5;
    if (blockIdx.x < 128) {
        const int c1 = blockIdx.x;
        __shared__ float ws[ROW];
        __shared__ float es[4 * D];
        const float* wrow = w1 + c1 * ROW;
        for (int i = tid; i < ROW; i += 256) ws[i] = wrow[i];
        for (int i = tid; i < 4 * D; i += 256) es[i] = emb[i];
        __syncthreads();
        if (tid < 36) {
            const int v = tid / KS, k1 = tid % KS;
            float s = 0.f;
            #pragma unroll 8
            for (int c0 = 0; c0 < D; c0++) s += ws[c0 * KS + k1] * es[v * D + c0];
            d_g1[(v * D + c1) * KS + k1] = s;
        }
    } else {
        __shared__ float b1s[D];
        if (tid < D) b1s[tid] = b1[tid];
        __syncthreads();
        const int c = (blockIdx.x - 128) * 8 + warp;
        const float* wrow = w2 + c * ROW;
        float s = 0.f;
        #pragma unroll
        for (int i = 0; i < ROW / 32; i++) {
            int idx = lane + 32 * i;
            s += wrow[idx] * b1s[idx / KS];
        }
        #pragma unroll
        for (int o = 16; o; o >>= 1) s += __shfl_xor_sync(0xffffffffu, s, o);
        if (lane == 0) d_bb2[c] = b2[c] + s;
    }
}

// ---------------------------------------------------------------------------
// pre2: one block per c2 row; reads W2 row ONCE, computes all 68 (v,t).
__global__ __launch_bounds__(256) void k_pre2(const float* __restrict__ w2)
{
    const int tid = threadIdx.x, lane = tid & 31, warp = tid >> 5;
    const int c2 = blockIdx.x;
    __shared__ float ws[ROW];
    __shared__ float g1s[4 * D * KS];
    const float* wrow = w2 + c2 * ROW;
    for (int i = tid; i < ROW; i += 256) ws[i] = wrow[i];
    for (int i = tid; i < 4 * D * KS; i += 256) g1s[i] = d_g1[i];
    __syncthreads();
    for (int pr = warp; pr < 68; pr += 8) {
        const int v = pr & 3, t = pr >> 2;
        const int klo = (t > KS - 1) ? t - (KS - 1) : 0;
        const int khi = (t < KS - 1) ? t : KS - 1;
        float s = 0.f;
        for (int k2 = klo; k2 <= khi; k2++) {
            const int k1 = t - k2;
            #pragma unroll
            for (int j = 0; j < 4; j++) {
                int c1 = lane + 32 * j;
                s += ws[c1 * KS + k2] * g1s[(v * D + c1) * KS + k1];
            }
        }
        #pragma unroll
        for (int o = 16; o; o >>= 1) s += __shfl_xor_sync(0xffffffffu, s, o);
        if (lane == 0) d_g2[(v * D + c2) * T12 + t] = s;
    }
}

// ---------------------------------------------------------------------------
// pre3: blocks [0,128): block per c3, all 100 (v,t) -> transposed d_G.
//       blocks [128,144): beff.
__global__ __launch_bounds__(256) void k_pre3(
    const float* __restrict__ w3, const float* __restrict__ b3)
{
    const int tid = threadIdx.x, lane = tid & 31, warp = tid >> 5;
    if (blockIdx.x < 128) {
        const int c3 = blockIdx.x;
        __shared__ float ws[ROW];
        __shared__ float g2s[4 * D * T12];
        const float* wrow = w3 + c3 * ROW;
        for (int i = tid; i < ROW; i += 256) ws[i] = wrow[i];
        for (int i = tid; i < 4 * D * T12; i += 256) g2s[i] = d_g2[i];
        __syncthreads();
        for (int pr = warp; pr < 100; pr += 8) {
            const int v = pr & 3, t = pr >> 2;
            const int klo = (t > T12 - 1) ? t - (T12 - 1) : 0;
            const int khi = (t < KS - 1) ? t : KS - 1;
            float s = 0.f;
            for (int k3 = klo; k3 <= khi; k3++) {
                const int t12 = t - k3;
                #pragma unroll
                for (int j = 0; j < 4; j++) {
                    int c2 = lane + 32 * j;
                    s += ws[c2 * KS + k3] * g2s[(v * D + c2) * T12 + t12];
                }
            }
            #pragma unroll
            for (int o = 16; o; o >>= 1) s += __shfl_xor_sync(0xffffffffu, s, o);
            if (lane == 0) d_G[(t * 4 + v) * D + c3] = s;   // transposed
        }
    } else {
        __shared__ float bbs[D];
        if (tid < D) bbs[tid] = d_bb2[tid];
        __syncthreads();
        const int c = (blockIdx.x - 128) * 8 + warp;
        const float* wrow = w3 + c * ROW;
        float s = 0.f;
        #pragma unroll
        for (int i = 0; i < ROW / 32; i++) {
            int idx = lane + 32 * i;
            s += wrow[idx] * bbs[idx / KS];
        }
        #pragma unroll
        for (int o = 16; o; o >>= 1) s += __shfl_xor_sync(0xffffffffu, s, o);
        if (lane == 0) d_beff[c] = b3[c] + s;
    }
}

// ---------------------------------------------------------------------------
// Main kernel: one CTA per batch row.
__global__ __launch_bounds__(1024) void k_main(
    const int*   __restrict__ tokens,
    const float* __restrict__ wq, const float* __restrict__ bq,
    const float* __restrict__ wk, const float* __restrict__ bk,
    const float* __restrict__ wv, const float* __restrict__ bv,
    float* __restrict__ out)
{
    __shared__ float sc[4096];           // scores/exp (padded) + matvec scratch
    __shared__ float Hq[6 * 256];        // quad tables
    __shared__ float Hs[128];            // H laid out [t*4+v]
    __shared__ float As[128];            // A laid out [t*4+v]
    __shared__ float cntf[128];          // windowed counts [t*4+v]
    __shared__ float rm[D], qv[D], qks[D], sv[D];
    __shared__ float redf[40];
    __shared__ int   cnti[4];
    __shared__ unsigned tok_u[1032];     // packed tokens + zero pad
    __shared__ unsigned pat_u[1032];     // packed 4-token patterns
    unsigned char* tok = (unsigned char*)tok_u;

    const int b = blockIdx.x, tid = threadIdx.x;
    const int lane = tid & 31, warp = tid >> 5;

    // Phase 0: stage tokens as packed bytes, zero padding
    {
        const int4* tb4 = (const int4*)(tokens + b * L_IN);
        int4 w = tb4[tid];
        tok_u[tid] = (unsigned)w.x | ((unsigned)w.y << 8) |
                     ((unsigned)w.z << 16) | ((unsigned)w.w << 24);
    }
    if (tid < 8) tok_u[1024 + tid] = 0;
    if (tid < 4) cnti[tid] = 0;
    __syncthreads();

    // Phase 0b: build pat (idx = 64*tok[j] + 16*tok[j+1] + 4*tok[j+2] + tok[j+3])
    for (int i = tid; i < 1030; i += 1024) {
        unsigned w0 = tok_u[i], w1 = tok_u[i + 1];
        unsigned p0 = ((w0 & 0x03030303u) * 0x40100401u) >> 24;
        unsigned f1 = __funnelshift_r(w0, w1, 8);
        unsigned p1 = ((f1 & 0x03030303u) * 0x40100401u) >> 24;
        unsigned f2 = __funnelshift_r(w0, w1, 16);
        unsigned p2 = ((f2 & 0x03030303u) * 0x40100401u) >> 24;
        unsigned f3 = __funnelshift_r(w0, w1, 24);
        unsigned p3 = ((f3 & 0x03030303u) * 0x40100401u) >> 24;
        pat_u[i] = p0 | (p1 << 8) | (p2 << 16) | (p3 << 24);
    }

    // Phase 1a: full-sequence token counts
    {
        unsigned u = tok_u[tid];
        int l0 = 0, l1 = 0, l2 = 0, l3 = 0;
        #pragma unroll
        for (int j = 0; j < 4; j++) {
            int v = (u >> (8 * j)) & 3;
            l0 += (v == 0); l1 += (v == 1); l2 += (v == 2); l3 += (v == 3);
        }
        #pragma unroll
        for (int o = 16; o; o >>= 1) {
            l0 += __shfl_xor_sync(0xffffffffu, l0, o);
            l1 += __shfl_xor_sync(0xffffffffu, l1, o);
            l2 += __shfl_xor_sync(0xffffffffu, l2, o);
            l3 += __shfl_xor_sync(0xffffffffu, l3, o);
        }
        if (lane == 0) {
            atomicAdd(&cnti[0], l0); atomicAdd(&cnti[1], l1);
            atomicAdd(&cnti[2], l2); atomicAdd(&cnti[3], l3);
        }
    }
    __syncthreads();

    // Phase 1b: windowed counts
    if (warp == 0 && lane < T_EFF) {
        int t = lane;
        int c0 = cnti[0], c1 = cnti[1], c2 = cnti[2], c3 = cnti[3];
        for (int j = 0; j < t; j++) {
            int v = tok[j];
            c0 -= (v == 0); c1 -= (v == 1); c2 -= (v == 2); c3 -= (v == 3);
        }
        for (int j = t + L_OUT; j < L_IN; j++) {
            int v = tok[j];
            c0 -= (v == 0); c1 -= (v == 1); c2 -= (v == 2); c3 -= (v == 3);
        }
        cntf[t * 4 + 0] = (float)c0; cntf[t * 4 + 1] = (float)c1;
        cntf[t * 4 + 2] = (float)c2; cntf[t * 4 + 3] = (float)c3;
    }
    __syncthreads();

    // Phase 1c: rm = beff + (cnt . Gt)/L_OUT  (coalesced, 8 partials per c)
    {
        int part = tid >> 7, c = tid & 127;
        int i0 = part * 13, i1 = (part == 7) ? 100 : i0 + 13;
        float acc = 0.f;
        for (int i = i0; i < i1; i++) acc += cntf[i] * d_G[i * D + c];
        sc[part * 128 + c] = acc;
    }
    __syncthreads();
    if (tid < D) {
        float acc = 0.f;
        #pragma unroll
        for (int p = 0; p < 8; p++) acc += sc[p * 128 + tid];
        rm[tid] = d_beff[tid] + acc * (1.0f / (float)L_OUT);
    }
    __syncthreads();

    // Phase 2: q = Wq @ rm + bq
    for (int c = warp; c < D; c += 32) {
        float s = 0.f;
        #pragma unroll
        for (int j = 0; j < 4; j++) { int i = lane + 32 * j; s += wq[c * D + i] * rm[i]; }
        #pragma unroll
        for (int o = 16; o; o >>= 1) s += __shfl_xor_sync(0xffffffffu, s, o);
        if (lane == 0) qv[c] = s + bq[c];
    }
    __syncthreads();

    // Phase 3: qk = Wk^T @ q
    {
        int g = tid >> 7, i = tid & 127;
        float s = 0.f;
        #pragma unroll
        for (int o = 0; o < 16; o++) s += wk[(g * 16 + o) * D + i] * qv[g * 16 + o];
        sc[g * D + i] = s;
    }
    __syncthreads();
    if (tid < D) {
        float s = 0.f;
        #pragma unroll
        for (int g = 0; g < 8; g++) s += sc[g * D + tid];
        qks[tid] = s;
    }
    __syncthreads();

    // Phase H: Hs[i] = qk . Gt[i][:]   (coalesced)
    for (int pr = warp; pr < 100; pr += 32) {
        float s = 0.f;
        #pragma unroll
        for (int j = 0; j < 4; j++) {
            int c = lane + 32 * j;
            s += qks[c] * d_G[pr * D + c];
        }
        #pragma unroll
        for (int o = 16; o; o >>= 1) s += __shfl_xor_sync(0xffffffffu, s, o);
        if (lane == 0) Hs[pr] = s;
    }
    __syncthreads();

    // Build quad tables Hq[q][idx] = sum_r Hs[(4q+r)*4 + b_r(idx)]
    for (int e = tid; e < 6 * 256; e += 1024) {
        int q = e >> 8, idx = e & 255;
        Hq[e] = Hs[(4 * q + 0) * 4 + ((idx >> 6) & 3)]
              + Hs[(4 * q + 1) * 4 + ((idx >> 4) & 3)]
              + Hs[(4 * q + 2) * 4 + ((idx >> 2) & 3)]
              + Hs[(4 * q + 3) * 4 + (idx & 3)];
    }
    __syncthreads();

    // Phase 4: scores via quad lookups
    const float isq = 0.088388347648318447f;  // 1/sqrt(128)
    float lmax = -1e30f;
    if (tid < 1018) {
        unsigned pw[6];
        #pragma unroll
        for (int q = 0; q < 6; q++) pw[q] = pat_u[tid + q];
        unsigned u6 = tok_u[tid + 6];
        const int l0 = tid * 4;
        #pragma unroll
        for (int k = 0; k < 4; k++) {
            float s = 0.f;
            #pragma unroll
            for (int q = 0; q < 6; q++)
                s += Hq[q * 256 + __byte_perm(pw[q], 0, 0x4440 + k)];
            s += Hs[96 + ((u6 >> (8 * k)) & 3)];
            s *= isq;
            sc[l0 + k] = s;
            lmax = fmaxf(lmax, s);
        }
    }
    #pragma unroll
    for (int o = 16; o; o >>= 1) lmax = fmaxf(lmax, __shfl_xor_sync(0xffffffffu, lmax, o));
    if (lane == 0) redf[warp] = lmax;
    __syncthreads();
    if (tid < 32) {
        float m = redf[tid];
        #pragma unroll
        for (int o = 16; o; o >>= 1) m = fmaxf(m, __shfl_xor_sync(0xffffffffu, m, o));
        if (tid == 0) redf[33] = m;
    }
    __syncthreads();
    const float smax = redf[33];

    // Phase 5: exp + sum; zero-pad sc[4072..4095]
    float lsum = 0.f;
    for (int l = tid; l < L_OUT; l += 1024) {
        float e = __expf(sc[l] - smax);
        sc[l] = e;
        lsum += e;
    }
    if (tid < 24) sc[L_OUT + tid] = 0.f;
    #pragma unroll
    for (int o = 16; o; o >>= 1) lsum += __shfl_xor_sync(0xffffffffu, lsum, o);
    if (lane == 0) redf[warp] = lsum;
    __syncthreads();
    if (tid < 32) {
        float m = redf[tid];
        #pragma unroll
        for (int o = 16; o; o >>= 1) m += __shfl_xor_sync(0xffffffffu, m, o);
        if (tid == 0) redf[34] = m;
    }
    __syncthreads();
    const float invZ = 1.0f / redf[34];

    // Phase 6: A[t*4+v] — warp per tap, guard-free (pads are zero)
    if (warp < T_EFF) {
        const int t = warp;
        float a0 = 0.f, a1 = 0.f, a2 = 0.f, a3 = 0.f;
        #pragma unroll 4
        for (int l = lane; l < 4096; l += 32) {
            float e = sc[l];
            int v = tok[l + t];
            if (v == 0) a0 += e;
            if (v == 1) a1 += e;
            if (v == 2) a2 += e;
            if (v == 3) a3 += e;
        }
        #pragma unroll
        for (int o = 16; o; o >>= 1) {
            a0 += __shfl_xor_sync(0xffffffffu, a0, o);
            a1 += __shfl_xor_sync(0xffffffffu, a1, o);
            a2 += __shfl_xor_sync(0xffffffffu, a2, o);
            a3 += __shfl_xor_sync(0xffffffffu, a3, o);
        }
        if (lane == 0) {
            As[t * 4 + 0] = a0; As[t * 4 + 1] = a1;
            As[t * 4 + 2] = a2; As[t * 4 + 3] = a3;
        }
    }
    __syncthreads();

    // Phase 7: sv = beff + invZ * (A . Gt)   (coalesced, 8 partials per c)
    {
        int part = tid >> 7, c = tid & 127;
        int i0 = part * 13, i1 = (part == 7) ? 100 : i0 + 13;
        float acc = 0.f;
        for (int i = i0; i < i1; i++) acc += As[i] * d_G[i * D + c];
        sc[part * 128 + c] = acc;
    }
    __syncthreads();
    if (tid < D) {
        float acc = 0.f;
        #pragma unroll
        for (int p = 0; p < 8; p++) acc += sc[p * 128 + tid];
        sv[tid] = d_beff[tid] + acc * invZ;
    }
    __syncthreads();

    // Phase 8: out = Wv @ sv + bv
    for (int c = warp; c < D; c += 32) {
        float s = 0.f;
        #pragma unroll
        for (int j = 0; j < 4; j++) { int i = lane + 32 * j; s += wv[c * D + i] * sv[i]; }
        #pragma unroll
        for (int o = 16; o; o >>= 1) s += __shfl_xor_sync(0xffffffffu, s, o);
        if (lane == 0) out[b * D + c] = s + bv[c];
    }
}

// ---------------------------------------------------------------------------
extern "C" void kernel_launch(void* const* d_in, const int* in_sizes, int n_in,
                              void* d_out, int out_size) {
    const int*   tokens = (const int*)  d_in[0];
    const float* emb    = (const float*)d_in[1];
    const float* w1     = (const float*)d_in[2];
    const float* b1     = (const float*)d_in[3];
    const float* wr     = (const float*)d_in[4];
    const float* br     = (const float*)d_in[5];
    const float* wq     = (const float*)d_in[6];
    const float* bq     = (const float*)d_in[7];
    const float* wk     = (const float*)d_in[8];
    const float* bk     = (const float*)d_in[9];
    const float* wv     = (const float*)d_in[10];
    const float* bv     = (const float*)d_in[11];

    const float* w2 = wr;
    const float* w3 = wr + D * D * KS;
    const float* b2 = br;
    const float* b3 = br + D;

    k_pre1<<<144, 256>>>(w1, emb, w2, b1, b2);
    k_pre2<<<128, 256>>>(w2);
    k_pre3<<<144, 256>>>(w3, b3);
    k_main<<<BATCH, 1024>>>(tokens, wq, bq, wk, bk, wv, bv, (float*)d_out);
}